// round 1
// baseline (speedup 1.0000x reference)
#include <cuda_runtime.h>
#include <math.h>

#define BB      16
#define HWN     589824            // 768*768
#define KBINS   (1 << 19)         // quantization bins; delta = 1/KBINS ~ 1.9e-6
#define CHUNK   4096
#define NCHUNK  (KBINS / CHUNK)   // 128
#define RCHUNK  128
#define MERGE_THREADS_PER_SAMPLE ((HWN + RCHUNK - 1) / RCHUNK)   // 4608

// Scratch (allocation-free rule: __device__ globals)
__device__ unsigned int g_cnt[2][BB][KBINS];      // [0]=pred hist/CDF, [1]=target; 64 MB
__device__ unsigned int g_csum[2][BB][NCHUNK];    // per-chunk totals -> offsets
__device__ double       g_acc;

// ---------------------------------------------------------------------------
// 1) sigmoid(x1-x0) + histogram of pred and target, per sample
// ---------------------------------------------------------------------------
__global__ void hist_kernel(const float* __restrict__ x, const float* __restrict__ t) {
    int b  = blockIdx.y;
    int hw = blockIdx.x * blockDim.x + threadIdx.x;       // grid sized exactly
    size_t basex = (size_t)b * 2 * HWN + hw;
    float x0 = x[basex];
    float x1 = x[basex + HWN];
    float v  = 1.0f / (1.0f + expf(x0 - x1));             // softmax ch1 of 2 == sigmoid
    int bp = (int)(v * (float)KBINS);
    bp = bp > KBINS - 1 ? KBINS - 1 : (bp < 0 ? 0 : bp);
    atomicAdd(&g_cnt[0][b][bp], 1u);

    float tv = t[(size_t)b * HWN + hw];
    int bq = (int)(tv * (float)KBINS);
    bq = bq > KBINS - 1 ? KBINS - 1 : (bq < 0 ? 0 : bq);
    atomicAdd(&g_cnt[1][b][bq], 1u);
}

// ---------------------------------------------------------------------------
// 2) inclusive prefix scan of each (array, sample) row of KBINS counters
//    a) per-chunk scan (4096 bins / block), record chunk totals
// ---------------------------------------------------------------------------
__global__ void scan_chunks() {
    __shared__ unsigned int warpsums[32];
    unsigned int* row = &g_cnt[blockIdx.z][blockIdx.y][0];
    int base = blockIdx.x * CHUNK + threadIdx.x * 4;

    uint4 v = *reinterpret_cast<uint4*>(&row[base]);
    v.y += v.x; v.z += v.y; v.w += v.z;                   // local inclusive
    unsigned tot = v.w;

    unsigned lane = threadIdx.x & 31, wid = threadIdx.x >> 5;
    unsigned s = tot;
    #pragma unroll
    for (int o = 1; o < 32; o <<= 1) {
        unsigned n = __shfl_up_sync(0xFFFFFFFFu, s, o);
        if (lane >= o) s += n;
    }
    if (lane == 31) warpsums[wid] = s;
    __syncthreads();
    if (wid == 0) {
        unsigned ws = warpsums[lane];
        #pragma unroll
        for (int o = 1; o < 32; o <<= 1) {
            unsigned n = __shfl_up_sync(0xFFFFFFFFu, ws, o);
            if (lane >= o) ws += n;
        }
        warpsums[lane] = ws;
    }
    __syncthreads();

    unsigned prefix = (s - tot) + (wid ? warpsums[wid - 1] : 0u); // exclusive for thread
    v.x += prefix; v.y += prefix; v.z += prefix; v.w += prefix;
    *reinterpret_cast<uint4*>(&row[base]) = v;
    if (threadIdx.x == 1023)
        g_csum[blockIdx.z][blockIdx.y][blockIdx.x] = v.w;
}

//    b) exclusive scan of the 128 chunk totals per row (one block per row)
__global__ void scan_offsets() {
    unsigned int* s = &g_csum[blockIdx.z][blockIdx.y][0];
    __shared__ unsigned sh[NCHUNK];
    sh[threadIdx.x] = s[threadIdx.x];
    __syncthreads();
    for (int o = 1; o < NCHUNK; o <<= 1) {
        unsigned add = (threadIdx.x >= (unsigned)o) ? sh[threadIdx.x - o] : 0u;
        __syncthreads();
        sh[threadIdx.x] += add;
        __syncthreads();
    }
    s[threadIdx.x] = threadIdx.x ? sh[threadIdx.x - 1] : 0u;  // exclusive
}

//    c) add chunk offsets -> global inclusive CDF in place
__global__ void add_offsets() {
    unsigned off = g_csum[blockIdx.z][blockIdx.y][blockIdx.x];
    if (off == 0u) return;                                   // chunk 0 / empty prefix
    unsigned int* row = &g_cnt[blockIdx.z][blockIdx.y][0];
    int base = blockIdx.x * CHUNK + threadIdx.x * 4;
    uint4 v = *reinterpret_cast<uint4*>(&row[base]);
    v.x += off; v.y += off; v.z += off; v.w += off;
    *reinterpret_cast<uint4*>(&row[base]) = v;
}

// ---------------------------------------------------------------------------
// 3) CDF merge: for each rank r, bin index of pred and target at that rank;
//    accumulate ((kp - kq) * delta)^2
// ---------------------------------------------------------------------------
__device__ __forceinline__ int upper_bound_cdf(const unsigned* __restrict__ cdf, unsigned r) {
    int lo = 0, hi = KBINS;
    while (lo < hi) {
        int mid = (lo + hi) >> 1;
        if (__ldg(&cdf[mid]) <= r) lo = mid + 1; else hi = mid;
    }
    return lo;   // smallest k with cdf[k] > r; cdf[KBINS-1] = HWN > r always
}

__device__ __forceinline__ double warpReduceD(double v) {
    #pragma unroll
    for (int o = 16; o > 0; o >>= 1) v += __shfl_down_sync(0xFFFFFFFFu, v, o);
    return v;
}

__global__ void merge_kernel() {
    int b   = blockIdx.y;
    int tix = blockIdx.x * blockDim.x + threadIdx.x;
    long r0 = (long)tix * RCHUNK;
    double local = 0.0;
    if (r0 < HWN) {
        int r1 = (int)((r0 + RCHUNK < HWN) ? (r0 + RCHUNK) : HWN);
        const unsigned* __restrict__ CP = g_cnt[0][b];
        const unsigned* __restrict__ CQ = g_cnt[1][b];
        int kp = upper_bound_cdf(CP, (unsigned)r0);
        int kq = upper_bound_cdf(CQ, (unsigned)r0);
        unsigned cp = __ldg(&CP[kp]);
        unsigned cq = __ldg(&CQ[kq]);
        const float ds = 1.0f / (float)KBINS;
        float acc = 0.0f;
        for (int r = (int)r0; r < r1; ++r) {
            while (cp <= (unsigned)r) cp = __ldg(&CP[++kp]);
            while (cq <= (unsigned)r) cq = __ldg(&CQ[++kq]);
            float d = (float)(kp - kq) * ds;
            acc = fmaf(d, d, acc);
        }
        local = (double)acc;
    }
    local = warpReduceD(local);
    __shared__ double sh[8];
    int lane = threadIdx.x & 31, wid = threadIdx.x >> 5;
    if (lane == 0) sh[wid] = local;
    __syncthreads();
    if (wid == 0) {
        double v = (lane < 8) ? sh[lane] : 0.0;
        v = warpReduceD(v);
        if (lane == 0) atomicAdd(&g_acc, v);
    }
}

__global__ void finalize_kernel(float* __restrict__ out) {
    out[0] = (float)(g_acc / ((double)BB * (double)HWN));
}

// ---------------------------------------------------------------------------
extern "C" void kernel_launch(void* const* d_in, const int* in_sizes, int n_in,
                              void* d_out, int out_size) {
    const float* x = (const float*)d_in[0];   // [16, 2, 768, 768]
    const float* t = (const float*)d_in[1];   // [16, 768, 768]
    float* out = (float*)d_out;               // scalar

    void* cnt_ptr = nullptr;
    void* acc_ptr = nullptr;
    cudaGetSymbolAddress(&cnt_ptr, g_cnt);
    cudaGetSymbolAddress(&acc_ptr, g_acc);

    cudaMemsetAsync(cnt_ptr, 0, sizeof(unsigned int) * 2 * BB * KBINS, 0);
    cudaMemsetAsync(acc_ptr, 0, sizeof(double), 0);

    hist_kernel<<<dim3(HWN / 256, BB), 256>>>(x, t);
    scan_chunks<<<dim3(NCHUNK, BB, 2), 1024>>>();
    scan_offsets<<<dim3(1, BB, 2), NCHUNK>>>();
    add_offsets<<<dim3(NCHUNK, BB, 2), 1024>>>();
    merge_kernel<<<dim3((MERGE_THREADS_PER_SAMPLE + 255) / 256, BB), 256>>>();
    finalize_kernel<<<1, 1>>>(out);
}

// round 2
// speedup vs baseline: 3.0289x; 3.0289x over previous
#include <cuda_runtime.h>
#include <math.h>

#define BB      16
#define HWN     589824            // 768*768
#define KBINS   (1 << 16)         // 65536 bins; counters = 8 MB -> L2-resident
#define CHUNK   4096
#define NCHUNK  (KBINS / CHUNK)   // 16
#define RCHUNK  128
#define MERGE_THREADS_PER_SAMPLE ((HWN + RCHUNK - 1) / RCHUNK)   // 4608

// Scratch (allocation-free rule: __device__ globals)
__device__ unsigned int g_cnt[2][BB][KBINS];      // [0]=pred hist/CDF, [1]=target; 8 MB
__device__ unsigned int g_csum[2][BB][NCHUNK];
__device__ double       g_acc;

// ---------------------------------------------------------------------------
// 1) sigmoid(x1-x0) + histogram of pred and target, per sample (float4 path)
// ---------------------------------------------------------------------------
__global__ void hist_kernel(const float* __restrict__ x, const float* __restrict__ t) {
    int b  = blockIdx.y;
    int i4 = (blockIdx.x * blockDim.x + threadIdx.x) * 4;   // grid sized exactly
    size_t basex = (size_t)b * 2 * HWN + i4;

    float4 x0 = *reinterpret_cast<const float4*>(&x[basex]);
    float4 x1 = *reinterpret_cast<const float4*>(&x[basex + HWN]);
    float4 tv = *reinterpret_cast<const float4*>(&t[(size_t)b * HWN + i4]);

    unsigned int* __restrict__ hp = g_cnt[0][b];
    unsigned int* __restrict__ hq = g_cnt[1][b];
    const float kf = (float)KBINS;

    #pragma unroll
    for (int j = 0; j < 4; ++j) {
        float d  = (j == 0 ? x0.x - x1.x : j == 1 ? x0.y - x1.y : j == 2 ? x0.z - x1.z : x0.w - x1.w);
        float v  = __fdividef(1.0f, 1.0f + __expf(d));
        int bp = (int)(v * kf);
        bp = bp > KBINS - 1 ? KBINS - 1 : (bp < 0 ? 0 : bp);
        atomicAdd(&hp[bp], 1u);
        float tj = (j == 0 ? tv.x : j == 1 ? tv.y : j == 2 ? tv.z : tv.w);
        int bq = (int)(tj * kf);
        bq = bq > KBINS - 1 ? KBINS - 1 : (bq < 0 ? 0 : bq);
        atomicAdd(&hq[bq], 1u);
    }
}

// ---------------------------------------------------------------------------
// 2) inclusive prefix scan of each (array, sample) row of KBINS counters
// ---------------------------------------------------------------------------
__global__ void scan_chunks() {
    __shared__ unsigned int warpsums[32];
    unsigned int* row = &g_cnt[blockIdx.z][blockIdx.y][0];
    int base = blockIdx.x * CHUNK + threadIdx.x * 4;

    uint4 v = *reinterpret_cast<uint4*>(&row[base]);
    v.y += v.x; v.z += v.y; v.w += v.z;                   // local inclusive
    unsigned tot = v.w;

    unsigned lane = threadIdx.x & 31, wid = threadIdx.x >> 5;
    unsigned s = tot;
    #pragma unroll
    for (int o = 1; o < 32; o <<= 1) {
        unsigned n = __shfl_up_sync(0xFFFFFFFFu, s, o);
        if (lane >= o) s += n;
    }
    if (lane == 31) warpsums[wid] = s;
    __syncthreads();
    if (wid == 0) {
        unsigned ws = warpsums[lane];
        #pragma unroll
        for (int o = 1; o < 32; o <<= 1) {
            unsigned n = __shfl_up_sync(0xFFFFFFFFu, ws, o);
            if (lane >= o) ws += n;
        }
        warpsums[lane] = ws;
    }
    __syncthreads();

    unsigned prefix = (s - tot) + (wid ? warpsums[wid - 1] : 0u); // exclusive for thread
    v.x += prefix; v.y += prefix; v.z += prefix; v.w += prefix;
    *reinterpret_cast<uint4*>(&row[base]) = v;
    if (threadIdx.x == 1023)
        g_csum[blockIdx.z][blockIdx.y][blockIdx.x] = v.w;
}

__global__ void scan_offsets() {
    unsigned int* s = &g_csum[blockIdx.z][blockIdx.y][0];
    __shared__ unsigned sh[NCHUNK];
    sh[threadIdx.x] = s[threadIdx.x];
    __syncthreads();
    for (int o = 1; o < NCHUNK; o <<= 1) {
        unsigned add = (threadIdx.x >= (unsigned)o) ? sh[threadIdx.x - o] : 0u;
        __syncthreads();
        sh[threadIdx.x] += add;
        __syncthreads();
    }
    s[threadIdx.x] = threadIdx.x ? sh[threadIdx.x - 1] : 0u;  // exclusive
}

__global__ void add_offsets() {
    unsigned off = g_csum[blockIdx.z][blockIdx.y][blockIdx.x];
    if (off == 0u) return;
    unsigned int* row = &g_cnt[blockIdx.z][blockIdx.y][0];
    int base = blockIdx.x * CHUNK + threadIdx.x * 4;
    uint4 v = *reinterpret_cast<uint4*>(&row[base]);
    v.x += off; v.y += off; v.z += off; v.w += off;
    *reinterpret_cast<uint4*>(&row[base]) = v;
}

// ---------------------------------------------------------------------------
// 3) CDF merge: for each rank r, accumulate ((kp - kq) * delta)^2
// ---------------------------------------------------------------------------
__device__ __forceinline__ int upper_bound_cdf(const unsigned* __restrict__ cdf, unsigned r) {
    int lo = 0, hi = KBINS;
    #pragma unroll 4
    while (lo < hi) {
        int mid = (lo + hi) >> 1;
        if (__ldg(&cdf[mid]) <= r) lo = mid + 1; else hi = mid;
    }
    return lo;   // smallest k with cdf[k] > r
}

__device__ __forceinline__ double warpReduceD(double v) {
    #pragma unroll
    for (int o = 16; o > 0; o >>= 1) v += __shfl_down_sync(0xFFFFFFFFu, v, o);
    return v;
}

__global__ void merge_kernel() {
    int b   = blockIdx.y;
    int tix = blockIdx.x * blockDim.x + threadIdx.x;
    long r0 = (long)tix * RCHUNK;
    double local = 0.0;
    if (r0 < HWN) {
        int r1 = (int)((r0 + RCHUNK < HWN) ? (r0 + RCHUNK) : HWN);
        const unsigned* __restrict__ CP = g_cnt[0][b];
        const unsigned* __restrict__ CQ = g_cnt[1][b];
        int kp = upper_bound_cdf(CP, (unsigned)r0);
        int kq = upper_bound_cdf(CQ, (unsigned)r0);
        unsigned cp = __ldg(&CP[kp]);
        unsigned cq = __ldg(&CQ[kq]);
        const float ds = 1.0f / (float)KBINS;
        float acc = 0.0f;
        for (int r = (int)r0; r < r1; ++r) {
            while (cp <= (unsigned)r) cp = __ldg(&CP[++kp]);
            while (cq <= (unsigned)r) cq = __ldg(&CQ[++kq]);
            float d = (float)(kp - kq) * ds;
            acc = fmaf(d, d, acc);
        }
        local = (double)acc;
    }
    local = warpReduceD(local);
    __shared__ double sh[8];
    int lane = threadIdx.x & 31, wid = threadIdx.x >> 5;
    if (lane == 0) sh[wid] = local;
    __syncthreads();
    if (wid == 0) {
        double v = (lane < 8) ? sh[lane] : 0.0;
        v = warpReduceD(v);
        if (lane == 0) atomicAdd(&g_acc, v);
    }
}

__global__ void finalize_kernel(float* __restrict__ out) {
    out[0] = (float)(g_acc / ((double)BB * (double)HWN));
}

// ---------------------------------------------------------------------------
extern "C" void kernel_launch(void* const* d_in, const int* in_sizes, int n_in,
                              void* d_out, int out_size) {
    const float* x = (const float*)d_in[0];   // [16, 2, 768, 768]
    const float* t = (const float*)d_in[1];   // [16, 768, 768]
    float* out = (float*)d_out;               // scalar

    void* cnt_ptr = nullptr;
    void* acc_ptr = nullptr;
    cudaGetSymbolAddress(&cnt_ptr, g_cnt);
    cudaGetSymbolAddress(&acc_ptr, g_acc);

    cudaMemsetAsync(cnt_ptr, 0, sizeof(unsigned int) * 2 * BB * KBINS, 0);
    cudaMemsetAsync(acc_ptr, 0, sizeof(double), 0);

    hist_kernel<<<dim3(HWN / (256 * 4), BB), 256>>>(x, t);
    scan_chunks<<<dim3(NCHUNK, BB, 2), 1024>>>();
    scan_offsets<<<dim3(1, BB, 2), NCHUNK>>>();
    add_offsets<<<dim3(NCHUNK, BB, 2), 1024>>>();
    merge_kernel<<<dim3((MERGE_THREADS_PER_SAMPLE + 255) / 256, BB), 256>>>();
    finalize_kernel<<<1, 1>>>(out);
}

// round 3
// speedup vs baseline: 3.1484x; 1.0394x over previous
#include <cuda_runtime.h>
#include <math.h>

#define BB      16
#define HWN     589824            // 768*768
#define KBINS   16384             // 2^14 bins; counters = 2 MB -> deep L2 residency
#define RCHUNK  256
#define TPS     (HWN / RCHUNK)    // 2304 merge threads per sample

// Scratch (allocation-free rule: __device__ globals)
__device__ unsigned int       g_cnt[2][BB][KBINS];   // [0]=pred, [1]=target; hist -> CDF in place
__device__ unsigned long long g_acc;                 // exact integer sum of (next-r)*(kp-kq)^2

// ---------------------------------------------------------------------------
// 1) sigmoid(x1-x0) + histogram of pred and target, per sample (float4 path)
// ---------------------------------------------------------------------------
__global__ void hist_kernel(const float* __restrict__ x, const float* __restrict__ t) {
    int b  = blockIdx.y;
    int i4 = (blockIdx.x * blockDim.x + threadIdx.x) * 4;   // grid sized exactly
    size_t basex = (size_t)b * 2 * HWN + i4;

    float4 x0 = *reinterpret_cast<const float4*>(&x[basex]);
    float4 x1 = *reinterpret_cast<const float4*>(&x[basex + HWN]);
    float4 tv = *reinterpret_cast<const float4*>(&t[(size_t)b * HWN + i4]);

    unsigned int* __restrict__ hp = g_cnt[0][b];
    unsigned int* __restrict__ hq = g_cnt[1][b];
    const float kf = (float)KBINS;

    #pragma unroll
    for (int j = 0; j < 4; ++j) {
        float d  = (j == 0 ? x0.x - x1.x : j == 1 ? x0.y - x1.y : j == 2 ? x0.z - x1.z : x0.w - x1.w);
        float v  = __fdividef(1.0f, 1.0f + __expf(d));
        int bp = (int)(v * kf);
        bp = bp > KBINS - 1 ? KBINS - 1 : (bp < 0 ? 0 : bp);
        atomicAdd(&hp[bp], 1u);
        float tj = (j == 0 ? tv.x : j == 1 ? tv.y : j == 2 ? tv.z : tv.w);
        int bq = (int)(tj * kf);
        bq = bq > KBINS - 1 ? KBINS - 1 : (bq < 0 ? 0 : bq);
        atomicAdd(&hq[bq], 1u);
    }
}

// ---------------------------------------------------------------------------
// 2) one block scans one entire (array, sample) row of 16384 counters
//    1024 threads x 16 elements, inclusive scan in place
// ---------------------------------------------------------------------------
__global__ void scan_rows() {
    __shared__ unsigned int warpsums[32];
    unsigned int* row = &g_cnt[blockIdx.y][blockIdx.x][0];   // (array, sample)
    int tbase = threadIdx.x * 16;

    uint4 v0 = *reinterpret_cast<uint4*>(&row[tbase + 0]);
    uint4 v1 = *reinterpret_cast<uint4*>(&row[tbase + 4]);
    uint4 v2 = *reinterpret_cast<uint4*>(&row[tbase + 8]);
    uint4 v3 = *reinterpret_cast<uint4*>(&row[tbase + 12]);

    // local inclusive chain over 16
    v0.y += v0.x; v0.z += v0.y; v0.w += v0.z;
    v1.x += v0.w; v1.y += v1.x; v1.z += v1.y; v1.w += v1.z;
    v2.x += v1.w; v2.y += v2.x; v2.z += v2.y; v2.w += v2.z;
    v3.x += v2.w; v3.y += v3.x; v3.z += v3.y; v3.w += v3.z;
    unsigned tot = v3.w;

    unsigned lane = threadIdx.x & 31, wid = threadIdx.x >> 5;
    unsigned s = tot;
    #pragma unroll
    for (int o = 1; o < 32; o <<= 1) {
        unsigned n = __shfl_up_sync(0xFFFFFFFFu, s, o);
        if (lane >= o) s += n;
    }
    if (lane == 31) warpsums[wid] = s;
    __syncthreads();
    if (wid == 0) {
        unsigned ws = warpsums[lane];
        #pragma unroll
        for (int o = 1; o < 32; o <<= 1) {
            unsigned n = __shfl_up_sync(0xFFFFFFFFu, ws, o);
            if (lane >= o) ws += n;
        }
        warpsums[lane] = ws;
    }
    __syncthreads();

    unsigned prefix = (s - tot) + (wid ? warpsums[wid - 1] : 0u);   // exclusive for thread
    v0.x += prefix; v0.y += prefix; v0.z += prefix; v0.w += prefix;
    v1.x += prefix; v1.y += prefix; v1.z += prefix; v1.w += prefix;
    v2.x += prefix; v2.y += prefix; v2.z += prefix; v2.w += prefix;
    v3.x += prefix; v3.y += prefix; v3.z += prefix; v3.w += prefix;

    *reinterpret_cast<uint4*>(&row[tbase + 0])  = v0;
    *reinterpret_cast<uint4*>(&row[tbase + 4])  = v1;
    *reinterpret_cast<uint4*>(&row[tbase + 8])  = v2;
    *reinterpret_cast<uint4*>(&row[tbase + 12]) = v3;
}

// ---------------------------------------------------------------------------
// 3) bin-space CDF merge: segments where (kp,kq) constant contribute
//    (seg_len) * (kp-kq)^2, exact u64 arithmetic
// ---------------------------------------------------------------------------
__device__ __forceinline__ int upper_bound_cdf(const unsigned* __restrict__ cdf, unsigned r) {
    int lo = 0, hi = KBINS;
    while (lo < hi) {
        int mid = (lo + hi) >> 1;
        if (__ldg(&cdf[mid]) <= r) lo = mid + 1; else hi = mid;
    }
    return lo;   // smallest k with cdf[k] > r; cdf[KBINS-1] = HWN > r always
}

__device__ __forceinline__ unsigned long long warpReduceU64(unsigned long long v) {
    #pragma unroll
    for (int o = 16; o > 0; o >>= 1) v += __shfl_down_sync(0xFFFFFFFFu, v, o);
    return v;
}

__global__ void merge_kernel() {
    int b   = blockIdx.y;
    int tix = blockIdx.x * blockDim.x + threadIdx.x;       // 0..TPS-1 (exact grid)
    unsigned r0 = (unsigned)tix * RCHUNK;
    unsigned r1 = r0 + RCHUNK;                             // HWN % RCHUNK == 0

    const unsigned* __restrict__ CP = g_cnt[0][b];
    const unsigned* __restrict__ CQ = g_cnt[1][b];

    int kp = upper_bound_cdf(CP, r0);
    int kq = upper_bound_cdf(CQ, r0);
    unsigned cp = __ldg(&CP[kp]);
    unsigned cq = __ldg(&CQ[kq]);

    unsigned long long local = 0ull;
    unsigned r = r0;
    while (r < r1) {
        unsigned next = cp < cq ? cp : cq;
        next = next < r1 ? next : r1;
        int dk = kp - kq;
        local += (unsigned long long)(next - r) * (unsigned long long)(dk * dk);
        r = next;
        if (r >= r1) break;
        while (cp <= r) cp = __ldg(&CP[++kp]);
        while (cq <= r) cq = __ldg(&CQ[++kq]);
    }

    local = warpReduceU64(local);
    __shared__ unsigned long long sh[8];
    int lane = threadIdx.x & 31, wid = threadIdx.x >> 5;
    if (lane == 0) sh[wid] = local;
    __syncthreads();
    if (wid == 0) {
        unsigned long long v = (lane < (int)(blockDim.x >> 5)) ? sh[lane] : 0ull;
        v = warpReduceU64(v);
        if (lane == 0) atomicAdd(&g_acc, v);
    }
}

__global__ void finalize_kernel(float* __restrict__ out) {
    const double ds = 1.0 / (double)KBINS;
    out[0] = (float)((double)g_acc * ds * ds / ((double)BB * (double)HWN));
}

// ---------------------------------------------------------------------------
extern "C" void kernel_launch(void* const* d_in, const int* in_sizes, int n_in,
                              void* d_out, int out_size) {
    const float* x = (const float*)d_in[0];   // [16, 2, 768, 768]
    const float* t = (const float*)d_in[1];   // [16, 768, 768]
    float* out = (float*)d_out;               // scalar

    void* cnt_ptr = nullptr;
    void* acc_ptr = nullptr;
    cudaGetSymbolAddress(&cnt_ptr, g_cnt);
    cudaGetSymbolAddress(&acc_ptr, g_acc);

    cudaMemsetAsync(cnt_ptr, 0, sizeof(unsigned int) * 2 * BB * KBINS, 0);
    cudaMemsetAsync(acc_ptr, 0, sizeof(unsigned long long), 0);

    hist_kernel<<<dim3(HWN / (256 * 4), BB), 256>>>(x, t);
    scan_rows<<<dim3(BB, 2), 1024>>>();
    merge_kernel<<<dim3(TPS / 256, BB), 256>>>();
    finalize_kernel<<<1, 1>>>(out);
}

// round 4
// speedup vs baseline: 10.8453x; 3.4447x over previous
#include <cuda_runtime.h>
#include <math.h>

#define BB      16
#define HWN     589824            // 768*768
#define KBINS   8192              // 2^13 bins; global counters = 1 MB, L2-resident
#define KH      (KBINS / 2)       // packed u16-pair words per histogram
#define HBLK    36                // hist blocks per sample
#define HTH     512
#define EPB     (HWN / HBLK)      // 16384 elements per block (u16-safe: < 65536)
#define HITER   (EPB / (HTH * 4)) // 8 float4 iterations per thread
#define RCHUNK  256
#define TPS     (HWN / RCHUNK)    // 2304 merge threads per sample

// Scratch (allocation-free rule: __device__ globals)
__device__ unsigned int       g_cnt[2][BB][KBINS];   // hist -> CDF in place
__device__ unsigned long long g_acc;

// ---------------------------------------------------------------------------
// 1) sigmoid(x1-x0) + SMEM-privatized histograms (u16-packed), flush as u64 REDs
// ---------------------------------------------------------------------------
__global__ void __launch_bounds__(HTH, 4)
hist_kernel(const float* __restrict__ x, const float* __restrict__ t) {
    __shared__ unsigned int sp[KH];   // pred hist, 2 x u16 per word
    __shared__ unsigned int sq[KH];   // target hist

    const int tid = threadIdx.x;
    const int b   = blockIdx.y;

    for (int i = tid; i < KH; i += HTH) { sp[i] = 0u; sq[i] = 0u; }
    __syncthreads();

    const size_t off = (size_t)blockIdx.x * EPB;
    const float* __restrict__ x0p = x + (size_t)b * 2 * HWN + off;
    const float* __restrict__ x1p = x0p + HWN;
    const float* __restrict__ tp  = t + (size_t)b * HWN + off;
    const float kf = (float)KBINS;

    #pragma unroll
    for (int it = 0; it < HITER; ++it) {
        int i4 = (it * HTH + tid) * 4;
        float4 a0 = *reinterpret_cast<const float4*>(&x0p[i4]);
        float4 a1 = *reinterpret_cast<const float4*>(&x1p[i4]);
        float4 tv = *reinterpret_cast<const float4*>(&tp[i4]);
        #pragma unroll
        for (int j = 0; j < 4; ++j) {
            float d  = (j == 0 ? a0.x - a1.x : j == 1 ? a0.y - a1.y : j == 2 ? a0.z - a1.z : a0.w - a1.w);
            float v  = __fdividef(1.0f, 1.0f + __expf(d));
            int bp = (int)(v * kf);
            bp = bp > KBINS - 1 ? KBINS - 1 : (bp < 0 ? 0 : bp);
            atomicAdd(&sp[bp >> 1], 1u << ((bp & 1) << 4));
            float tj = (j == 0 ? tv.x : j == 1 ? tv.y : j == 2 ? tv.z : tv.w);
            int bq = (int)(tj * kf);
            bq = bq > KBINS - 1 ? KBINS - 1 : (bq < 0 ? 0 : bq);
            atomicAdd(&sq[bq >> 1], 1u << ((bq & 1) << 4));
        }
    }
    __syncthreads();

    // Flush: packed word -> one u64 atomic covering bins (2w, 2w+1).
    // Halves stay < 2^32 forever, so no cross-half carry can occur.
    unsigned long long* __restrict__ gp = reinterpret_cast<unsigned long long*>(&g_cnt[0][b][0]);
    unsigned long long* __restrict__ gq = reinterpret_cast<unsigned long long*>(&g_cnt[1][b][0]);
    for (int w = tid; w < KH; w += HTH) {
        unsigned v = sp[w];
        if (v) atomicAdd(&gp[w], (unsigned long long)(v & 0xFFFFu) |
                                 ((unsigned long long)(v >> 16) << 32));
        v = sq[w];
        if (v) atomicAdd(&gq[w], (unsigned long long)(v & 0xFFFFu) |
                                 ((unsigned long long)(v >> 16) << 32));
    }
}

// ---------------------------------------------------------------------------
// 2) one block scans one entire (array, sample) row of 8192 counters
// ---------------------------------------------------------------------------
__global__ void scan_rows() {
    __shared__ unsigned int warpsums[32];
    unsigned int* row = &g_cnt[blockIdx.y][blockIdx.x][0];
    int tbase = threadIdx.x * 8;

    uint4 v0 = *reinterpret_cast<uint4*>(&row[tbase + 0]);
    uint4 v1 = *reinterpret_cast<uint4*>(&row[tbase + 4]);

    v0.y += v0.x; v0.z += v0.y; v0.w += v0.z;
    v1.x += v0.w; v1.y += v1.x; v1.z += v1.y; v1.w += v1.z;
    unsigned tot = v1.w;

    unsigned lane = threadIdx.x & 31, wid = threadIdx.x >> 5;
    unsigned s = tot;
    #pragma unroll
    for (int o = 1; o < 32; o <<= 1) {
        unsigned n = __shfl_up_sync(0xFFFFFFFFu, s, o);
        if (lane >= o) s += n;
    }
    if (lane == 31) warpsums[wid] = s;
    __syncthreads();
    if (wid == 0) {
        unsigned ws = warpsums[lane];
        #pragma unroll
        for (int o = 1; o < 32; o <<= 1) {
            unsigned n = __shfl_up_sync(0xFFFFFFFFu, ws, o);
            if (lane >= o) ws += n;
        }
        warpsums[lane] = ws;
    }
    __syncthreads();

    unsigned prefix = (s - tot) + (wid ? warpsums[wid - 1] : 0u);
    v0.x += prefix; v0.y += prefix; v0.z += prefix; v0.w += prefix;
    v1.x += prefix; v1.y += prefix; v1.z += prefix; v1.w += prefix;

    *reinterpret_cast<uint4*>(&row[tbase + 0]) = v0;
    *reinterpret_cast<uint4*>(&row[tbase + 4]) = v1;
}

// ---------------------------------------------------------------------------
// 3) bin-space CDF merge, exact u64 arithmetic
// ---------------------------------------------------------------------------
__device__ __forceinline__ int upper_bound_cdf(const unsigned* __restrict__ cdf, unsigned r) {
    int lo = 0, hi = KBINS;
    while (lo < hi) {
        int mid = (lo + hi) >> 1;
        if (__ldg(&cdf[mid]) <= r) lo = mid + 1; else hi = mid;
    }
    return lo;
}

__device__ __forceinline__ unsigned long long warpReduceU64(unsigned long long v) {
    #pragma unroll
    for (int o = 16; o > 0; o >>= 1) v += __shfl_down_sync(0xFFFFFFFFu, v, o);
    return v;
}

__global__ void merge_kernel() {
    int b   = blockIdx.y;
    int tix = blockIdx.x * blockDim.x + threadIdx.x;
    unsigned r0 = (unsigned)tix * RCHUNK;
    unsigned r1 = r0 + RCHUNK;

    const unsigned* __restrict__ CP = g_cnt[0][b];
    const unsigned* __restrict__ CQ = g_cnt[1][b];

    int kp = upper_bound_cdf(CP, r0);
    int kq = upper_bound_cdf(CQ, r0);
    unsigned cp = __ldg(&CP[kp]);
    unsigned cq = __ldg(&CQ[kq]);

    unsigned long long local = 0ull;
    unsigned r = r0;
    while (r < r1) {
        unsigned next = cp < cq ? cp : cq;
        next = next < r1 ? next : r1;
        int dk = kp - kq;
        local += (unsigned long long)(next - r) * (unsigned long long)(dk * dk);
        r = next;
        if (r >= r1) break;
        while (cp <= r) cp = __ldg(&CP[++kp]);
        while (cq <= r) cq = __ldg(&CQ[++kq]);
    }

    local = warpReduceU64(local);
    __shared__ unsigned long long sh[8];
    int lane = threadIdx.x & 31, wid = threadIdx.x >> 5;
    if (lane == 0) sh[wid] = local;
    __syncthreads();
    if (wid == 0) {
        unsigned long long v = (lane < (int)(blockDim.x >> 5)) ? sh[lane] : 0ull;
        v = warpReduceU64(v);
        if (lane == 0) atomicAdd(&g_acc, v);
    }
}

__global__ void finalize_kernel(float* __restrict__ out) {
    const double ds = 1.0 / (double)KBINS;
    out[0] = (float)((double)g_acc * ds * ds / ((double)BB * (double)HWN));
}

// ---------------------------------------------------------------------------
extern "C" void kernel_launch(void* const* d_in, const int* in_sizes, int n_in,
                              void* d_out, int out_size) {
    const float* x = (const float*)d_in[0];   // [16, 2, 768, 768]
    const float* t = (const float*)d_in[1];   // [16, 768, 768]
    float* out = (float*)d_out;               // scalar

    void* cnt_ptr = nullptr;
    void* acc_ptr = nullptr;
    cudaGetSymbolAddress(&cnt_ptr, g_cnt);
    cudaGetSymbolAddress(&acc_ptr, g_acc);

    cudaMemsetAsync(cnt_ptr, 0, sizeof(unsigned int) * 2 * BB * KBINS, 0);
    cudaMemsetAsync(acc_ptr, 0, sizeof(unsigned long long), 0);

    hist_kernel<<<dim3(HBLK, BB), HTH>>>(x, t);
    scan_rows<<<dim3(BB, 2), 1024>>>();
    merge_kernel<<<dim3(TPS / 256, BB), 256>>>();
    finalize_kernel<<<1, 1>>>(out);
}

// round 5
// speedup vs baseline: 12.2647x; 1.1309x over previous
#include <cuda_runtime.h>
#include <math.h>

#define BB      16
#define HWN     589824            // 768*768
#define KBINS   8192              // 2^13 bins; counters = 1 MB, L2-resident
#define KH      (KBINS / 2)       // packed u16-pair words per histogram
#define HBLK    36                // hist blocks per sample
#define HTH     512
#define EPB     (HWN / HBLK)      // 16384 elements per block (u16-safe)
#define HITER   (EPB / (HTH * 4)) // 8 float4 iterations per thread
#define FTH     1024
#define RPT     (HWN / FTH)       // 576 ranks per fused-kernel thread

// Scratch (allocation-free rule: __device__ globals)
__device__ unsigned int       g_cnt[2][BB][KBINS];   // raw histograms (scan happens in smem)
__device__ unsigned long long g_acc;
__device__ unsigned int       g_done = 0;

// ---------------------------------------------------------------------------
// 1) sigmoid(x1-x0) + SMEM-privatized histograms (u16-packed), flush as u64 REDs
// ---------------------------------------------------------------------------
__global__ void __launch_bounds__(HTH, 4)
hist_kernel(const float* __restrict__ x, const float* __restrict__ t) {
    __shared__ unsigned int sp[KH];
    __shared__ unsigned int sq[KH];

    const int tid = threadIdx.x;
    const int b   = blockIdx.y;

    if (blockIdx.x == 0 && b == 0 && tid == 0) g_acc = 0ull;   // for the fused kernel

    for (int i = tid; i < KH; i += HTH) { sp[i] = 0u; sq[i] = 0u; }
    __syncthreads();

    const size_t off = (size_t)blockIdx.x * EPB;
    const float* __restrict__ x0p = x + (size_t)b * 2 * HWN + off;
    const float* __restrict__ x1p = x0p + HWN;
    const float* __restrict__ tp  = t + (size_t)b * HWN + off;
    const float kf = (float)KBINS;

    #pragma unroll
    for (int it = 0; it < HITER; ++it) {
        int i4 = (it * HTH + tid) * 4;
        float4 a0 = *reinterpret_cast<const float4*>(&x0p[i4]);
        float4 a1 = *reinterpret_cast<const float4*>(&x1p[i4]);
        float4 tv = *reinterpret_cast<const float4*>(&tp[i4]);
        #pragma unroll
        for (int j = 0; j < 4; ++j) {
            float d  = (j == 0 ? a0.x - a1.x : j == 1 ? a0.y - a1.y : j == 2 ? a0.z - a1.z : a0.w - a1.w);
            float v  = __fdividef(1.0f, 1.0f + __expf(d));
            int bp = (int)(v * kf);
            bp = bp > KBINS - 1 ? KBINS - 1 : (bp < 0 ? 0 : bp);
            atomicAdd(&sp[bp >> 1], 1u << ((bp & 1) << 4));
            float tj = (j == 0 ? tv.x : j == 1 ? tv.y : j == 2 ? tv.z : tv.w);
            int bq = (int)(tj * kf);
            bq = bq > KBINS - 1 ? KBINS - 1 : (bq < 0 ? 0 : bq);
            atomicAdd(&sq[bq >> 1], 1u << ((bq & 1) << 4));
        }
    }
    __syncthreads();

    unsigned long long* __restrict__ gp = reinterpret_cast<unsigned long long*>(&g_cnt[0][b][0]);
    unsigned long long* __restrict__ gq = reinterpret_cast<unsigned long long*>(&g_cnt[1][b][0]);
    for (int w = tid; w < KH; w += HTH) {
        unsigned v = sp[w];
        if (v) atomicAdd(&gp[w], (unsigned long long)(v & 0xFFFFu) |
                                 ((unsigned long long)(v >> 16) << 32));
        v = sq[w];
        if (v) atomicAdd(&gq[w], (unsigned long long)(v & 0xFFFFu) |
                                 ((unsigned long long)(v >> 16) << 32));
    }
}

// ---------------------------------------------------------------------------
// 2) fused: per-sample scan (in smem) + bin-space merge + last-block finalize
// ---------------------------------------------------------------------------
__device__ __forceinline__ void scan_row_to_smem(const unsigned* __restrict__ row,
                                                 unsigned* __restrict__ dst,
                                                 unsigned* warpsums, int tid) {
    int base = tid * 8;
    uint4 v0 = *reinterpret_cast<const uint4*>(&row[base + 0]);
    uint4 v1 = *reinterpret_cast<const uint4*>(&row[base + 4]);

    v0.y += v0.x; v0.z += v0.y; v0.w += v0.z;
    v1.x += v0.w; v1.y += v1.x; v1.z += v1.y; v1.w += v1.z;
    unsigned tot = v1.w;

    unsigned lane = tid & 31, wid = tid >> 5;
    unsigned s = tot;
    #pragma unroll
    for (int o = 1; o < 32; o <<= 1) {
        unsigned n = __shfl_up_sync(0xFFFFFFFFu, s, o);
        if (lane >= o) s += n;
    }
    if (lane == 31) warpsums[wid] = s;
    __syncthreads();
    if (wid == 0) {
        unsigned ws = warpsums[lane];
        #pragma unroll
        for (int o = 1; o < 32; o <<= 1) {
            unsigned n = __shfl_up_sync(0xFFFFFFFFu, ws, o);
            if (lane >= o) ws += n;
        }
        warpsums[lane] = ws;
    }
    __syncthreads();

    unsigned prefix = (s - tot) + (wid ? warpsums[wid - 1] : 0u);
    v0.x += prefix; v0.y += prefix; v0.z += prefix; v0.w += prefix;
    v1.x += prefix; v1.y += prefix; v1.z += prefix; v1.w += prefix;
    *reinterpret_cast<uint4*>(&dst[base + 0]) = v0;
    *reinterpret_cast<uint4*>(&dst[base + 4]) = v1;
}

__device__ __forceinline__ int upper_bound_sm(const unsigned* __restrict__ cdf, unsigned r) {
    int lo = 0, hi = KBINS;
    while (lo < hi) {
        int mid = (lo + hi) >> 1;
        if (cdf[mid] <= r) lo = mid + 1; else hi = mid;
    }
    return lo;
}

__device__ __forceinline__ unsigned long long warpReduceU64(unsigned long long v) {
    #pragma unroll
    for (int o = 16; o > 0; o >>= 1) v += __shfl_down_sync(0xFFFFFFFFu, v, o);
    return v;
}

__global__ void __launch_bounds__(FTH, 1)
fused_kernel(float* __restrict__ out) {
    extern __shared__ unsigned sh[];                 // sp[KBINS] | sq[KBINS]
    unsigned* sp = sh;
    unsigned* sq = sh + KBINS;
    __shared__ unsigned warpsums[32];
    __shared__ unsigned long long shred[32];

    const int b   = blockIdx.x;
    const int tid = threadIdx.x;

    scan_row_to_smem(&g_cnt[0][b][0], sp, warpsums, tid);
    __syncthreads();
    scan_row_to_smem(&g_cnt[1][b][0], sq, warpsums, tid);
    __syncthreads();

    // bin-space merge of ranks [tid*RPT, (tid+1)*RPT)
    unsigned r0 = (unsigned)tid * RPT;
    unsigned r1 = r0 + RPT;
    int kp = upper_bound_sm(sp, r0);
    int kq = upper_bound_sm(sq, r0);
    unsigned cp = sp[kp];
    unsigned cq = sq[kq];

    unsigned long long local = 0ull;
    unsigned r = r0;
    while (r < r1) {
        unsigned next = cp < cq ? cp : cq;
        next = next < r1 ? next : r1;
        int dk = kp - kq;
        local += (unsigned long long)(next - r) * (unsigned long long)(dk * dk);
        r = next;
        if (r >= r1) break;
        while (cp <= r) cp = sp[++kp];
        while (cq <= r) cq = sq[++kq];
    }

    local = warpReduceU64(local);
    int lane = tid & 31, wid = tid >> 5;
    if (lane == 0) shred[wid] = local;
    __syncthreads();
    if (wid == 0) {
        unsigned long long v = (lane < (FTH >> 5)) ? shred[lane] : 0ull;
        v = warpReduceU64(v);
        if (lane == 0) {
            atomicAdd(&g_acc, v);
            __threadfence();
            unsigned old = atomicAdd(&g_done, 1u);
            if (old == BB - 1) {                      // last block finalizes
                g_done = 0;                           // self-reset for graph replay
                unsigned long long total = *(volatile unsigned long long*)&g_acc;
                const double ds = 1.0 / (double)KBINS;
                out[0] = (float)((double)total * ds * ds / ((double)BB * (double)HWN));
            }
        }
    }
}

// ---------------------------------------------------------------------------
extern "C" void kernel_launch(void* const* d_in, const int* in_sizes, int n_in,
                              void* d_out, int out_size) {
    const float* x = (const float*)d_in[0];   // [16, 2, 768, 768]
    const float* t = (const float*)d_in[1];   // [16, 768, 768]
    float* out = (float*)d_out;               // scalar

    void* cnt_ptr = nullptr;
    cudaGetSymbolAddress(&cnt_ptr, g_cnt);
    cudaMemsetAsync(cnt_ptr, 0, sizeof(unsigned int) * 2 * BB * KBINS, 0);

    const int smem_bytes = 2 * KBINS * sizeof(unsigned);  // 64 KB
    static int attr_set = 0;
    if (!attr_set) {
        cudaFuncSetAttribute(fused_kernel, cudaFuncAttributeMaxDynamicSharedMemorySize,
                             smem_bytes);
        attr_set = 1;
    }

    hist_kernel<<<dim3(HBLK, BB), HTH>>>(x, t);
    fused_kernel<<<BB, FTH, smem_bytes>>>(out);
}

// round 6
// speedup vs baseline: 14.2808x; 1.1644x over previous
#include <cuda_runtime.h>
#include <math.h>

#define BB      16
#define HWN     589824            // 768*768
#define KBINS   8192              // 2^13 bins; counters = 1 MB, L2-resident
#define KH      (KBINS / 2)       // packed u16-pair words per histogram
#define HBLK    36                // hist blocks per sample
#define HTH     512
#define EPB     (HWN / HBLK)      // 16384 elements per block (u16-safe)
#define HITER   (EPB / (HTH * 4)) // 8 float4 iterations per thread
#define FTH     1024
#define SLICES  8                 // merge slices per sample -> 128 blocks total
#define RPT     (HWN / (SLICES * FTH))   // 72 ranks per fused-kernel thread

// Scratch (allocation-free rule: __device__ globals)
__device__ unsigned int       g_cnt[2][BB][KBINS];   // raw histograms (scan happens in smem)
__device__ unsigned long long g_acc;
__device__ unsigned int       g_done = 0;

// ---------------------------------------------------------------------------
// 1) sigmoid(x1-x0) + SMEM-privatized histograms (u16-packed), flush as u64 REDs
// ---------------------------------------------------------------------------
__global__ void __launch_bounds__(HTH, 4)
hist_kernel(const float* __restrict__ x, const float* __restrict__ t) {
    __shared__ unsigned int sp[KH];
    __shared__ unsigned int sq[KH];

    const int tid = threadIdx.x;
    const int b   = blockIdx.y;

    if (blockIdx.x == 0 && b == 0 && tid == 0) g_acc = 0ull;   // for the fused kernel

    for (int i = tid; i < KH; i += HTH) { sp[i] = 0u; sq[i] = 0u; }
    __syncthreads();

    const size_t off = (size_t)blockIdx.x * EPB;
    const float* __restrict__ x0p = x + (size_t)b * 2 * HWN + off;
    const float* __restrict__ x1p = x0p + HWN;
    const float* __restrict__ tp  = t + (size_t)b * HWN + off;
    const float kf = (float)KBINS;

    #pragma unroll
    for (int it = 0; it < HITER; ++it) {
        int i4 = (it * HTH + tid) * 4;
        float4 a0 = *reinterpret_cast<const float4*>(&x0p[i4]);
        float4 a1 = *reinterpret_cast<const float4*>(&x1p[i4]);
        float4 tv = *reinterpret_cast<const float4*>(&tp[i4]);
        #pragma unroll
        for (int j = 0; j < 4; ++j) {
            float d  = (j == 0 ? a0.x - a1.x : j == 1 ? a0.y - a1.y : j == 2 ? a0.z - a1.z : a0.w - a1.w);
            float v  = __fdividef(1.0f, 1.0f + __expf(d));
            int bp = (int)(v * kf);
            bp = bp > KBINS - 1 ? KBINS - 1 : (bp < 0 ? 0 : bp);
            atomicAdd(&sp[bp >> 1], 1u << ((bp & 1) << 4));
            float tj = (j == 0 ? tv.x : j == 1 ? tv.y : j == 2 ? tv.z : tv.w);
            int bq = (int)(tj * kf);
            bq = bq > KBINS - 1 ? KBINS - 1 : (bq < 0 ? 0 : bq);
            atomicAdd(&sq[bq >> 1], 1u << ((bq & 1) << 4));
        }
    }
    __syncthreads();

    unsigned long long* __restrict__ gp = reinterpret_cast<unsigned long long*>(&g_cnt[0][b][0]);
    unsigned long long* __restrict__ gq = reinterpret_cast<unsigned long long*>(&g_cnt[1][b][0]);
    for (int w = tid; w < KH; w += HTH) {
        unsigned v = sp[w];
        if (v) atomicAdd(&gp[w], (unsigned long long)(v & 0xFFFFu) |
                                 ((unsigned long long)(v >> 16) << 32));
        v = sq[w];
        if (v) atomicAdd(&gq[w], (unsigned long long)(v & 0xFFFFu) |
                                 ((unsigned long long)(v >> 16) << 32));
    }
}

// ---------------------------------------------------------------------------
// 2) fused: per-(sample,slice) block: scan rows to smem + merge slice + finalize
// ---------------------------------------------------------------------------
__device__ __forceinline__ void scan_row_to_smem(const unsigned* __restrict__ row,
                                                 unsigned* __restrict__ dst,
                                                 unsigned* warpsums, int tid) {
    int base = tid * 8;
    uint4 v0 = *reinterpret_cast<const uint4*>(&row[base + 0]);
    uint4 v1 = *reinterpret_cast<const uint4*>(&row[base + 4]);

    v0.y += v0.x; v0.z += v0.y; v0.w += v0.z;
    v1.x += v0.w; v1.y += v1.x; v1.z += v1.y; v1.w += v1.z;
    unsigned tot = v1.w;

    unsigned lane = tid & 31, wid = tid >> 5;
    unsigned s = tot;
    #pragma unroll
    for (int o = 1; o < 32; o <<= 1) {
        unsigned n = __shfl_up_sync(0xFFFFFFFFu, s, o);
        if (lane >= o) s += n;
    }
    if (lane == 31) warpsums[wid] = s;
    __syncthreads();
    if (wid == 0) {
        unsigned ws = warpsums[lane];
        #pragma unroll
        for (int o = 1; o < 32; o <<= 1) {
            unsigned n = __shfl_up_sync(0xFFFFFFFFu, ws, o);
            if (lane >= o) ws += n;
        }
        warpsums[lane] = ws;
    }
    __syncthreads();

    unsigned prefix = (s - tot) + (wid ? warpsums[wid - 1] : 0u);
    v0.x += prefix; v0.y += prefix; v0.z += prefix; v0.w += prefix;
    v1.x += prefix; v1.y += prefix; v1.z += prefix; v1.w += prefix;
    *reinterpret_cast<uint4*>(&dst[base + 0]) = v0;
    *reinterpret_cast<uint4*>(&dst[base + 4]) = v1;
}

__device__ __forceinline__ int upper_bound_sm(const unsigned* __restrict__ cdf, unsigned r) {
    int lo = 0, hi = KBINS;
    while (lo < hi) {
        int mid = (lo + hi) >> 1;
        if (cdf[mid] <= r) lo = mid + 1; else hi = mid;
    }
    return lo;
}

__device__ __forceinline__ unsigned long long warpReduceU64(unsigned long long v) {
    #pragma unroll
    for (int o = 16; o > 0; o >>= 1) v += __shfl_down_sync(0xFFFFFFFFu, v, o);
    return v;
}

__global__ void __launch_bounds__(FTH, 1)
fused_kernel(float* __restrict__ out) {
    extern __shared__ unsigned sh[];                 // sp[KBINS] | sq[KBINS]
    unsigned* sp = sh;
    unsigned* sq = sh + KBINS;
    __shared__ unsigned warpsums[32];
    __shared__ unsigned long long shred[32];

    const int b     = blockIdx.y;
    const int slice = blockIdx.x;
    const int tid   = threadIdx.x;

    scan_row_to_smem(&g_cnt[0][b][0], sp, warpsums, tid);
    __syncthreads();
    scan_row_to_smem(&g_cnt[1][b][0], sq, warpsums, tid);
    __syncthreads();

    // bin-space merge of this block's rank slice
    unsigned r0 = ((unsigned)slice * FTH + tid) * RPT;
    unsigned r1 = r0 + RPT;
    int kp = upper_bound_sm(sp, r0);
    int kq = upper_bound_sm(sq, r0);
    unsigned cp = sp[kp];
    unsigned cq = sq[kq];

    unsigned long long local = 0ull;
    unsigned r = r0;
    while (r < r1) {
        unsigned next = cp < cq ? cp : cq;
        next = next < r1 ? next : r1;
        int dk = kp - kq;
        local += (unsigned long long)(next - r) * (unsigned long long)(dk * dk);
        r = next;
        if (r >= r1) break;
        while (cp <= r) cp = sp[++kp];
        while (cq <= r) cq = sq[++kq];
    }

    local = warpReduceU64(local);
    int lane = tid & 31, wid = tid >> 5;
    if (lane == 0) shred[wid] = local;
    __syncthreads();
    if (wid == 0) {
        unsigned long long v = (lane < (FTH >> 5)) ? shred[lane] : 0ull;
        v = warpReduceU64(v);
        if (lane == 0) {
            atomicAdd(&g_acc, v);
            __threadfence();
            unsigned old = atomicAdd(&g_done, 1u);
            if (old == BB * SLICES - 1) {             // last block finalizes
                g_done = 0;                           // self-reset for graph replay
                unsigned long long total = *(volatile unsigned long long*)&g_acc;
                const double ds = 1.0 / (double)KBINS;
                out[0] = (float)((double)total * ds * ds / ((double)BB * (double)HWN));
            }
        }
    }
}

// ---------------------------------------------------------------------------
extern "C" void kernel_launch(void* const* d_in, const int* in_sizes, int n_in,
                              void* d_out, int out_size) {
    const float* x = (const float*)d_in[0];   // [16, 2, 768, 768]
    const float* t = (const float*)d_in[1];   // [16, 768, 768]
    float* out = (float*)d_out;               // scalar

    void* cnt_ptr = nullptr;
    cudaGetSymbolAddress(&cnt_ptr, g_cnt);
    cudaMemsetAsync(cnt_ptr, 0, sizeof(unsigned int) * 2 * BB * KBINS, 0);

    const int smem_bytes = 2 * KBINS * sizeof(unsigned);  // 64 KB
    static int attr_set = 0;
    if (!attr_set) {
        cudaFuncSetAttribute(fused_kernel, cudaFuncAttributeMaxDynamicSharedMemorySize,
                             smem_bytes);
        attr_set = 1;
    }

    hist_kernel<<<dim3(HBLK, BB), HTH>>>(x, t);
    fused_kernel<<<dim3(SLICES, BB), FTH, smem_bytes>>>(out);
}